// round 16
// baseline (speedup 1.0000x reference)
#include <cuda_runtime.h>
#include <cuda_bf16.h>
#include <cuda_fp16.h>
#include <cstdint>

#define D 128
#define TILE_M 128
#define SLOT_CAP 96
#define MAXN 65536
#define LN_EPS 1e-5f
#define NBLK 148
#define GEMM_THREADS 512   // 16 warps: 8 row-groups x 2 n-halves

// W' smem row stride: 128 bf16 = 256B + 16B pad = 272B (ldmatrix conflict-free)
#define WROW 272

// Scratch (static; no allocations allowed)
__device__ int    g_fmt64;
__device__ int    g_tile_ctr;                       // dynamic tile counter (reset each replay)
__device__ int    g_deg[MAXN];
__device__ int    g_slots[(size_t)MAXN * SLOT_CAP];
__device__ __half g_Gl[(size_t)MAXN * D];           // X @ Wl^T   (fp16 -> half gather traffic)
__device__ float  g_Gr[(size_t)MAXN * D];           // X @ Wr^T   (fp32)

// ---------------- build kernels ----------------
__global__ void zero_probe_kernel(const int* __restrict__ ei32, int n) {
    int i = blockIdx.x * blockDim.x + threadIdx.x;
    if (i < n) g_deg[i] = 0;
    if (i == 0) g_tile_ctr = 0;
    if (blockIdx.x == 0) {
        __shared__ int zc;
        if (threadIdx.x == 0) zc = 0;
        __syncthreads();
        int local = 0;
        #pragma unroll
        for (int j = 0; j < 4; j++) {
            int pos = 2 * (threadIdx.x + 256 * j) + 1;
            if (ei32[pos] == 0) local++;
        }
        atomicAdd(&zc, local);
        __syncthreads();
        if (threadIdx.x == 0) g_fmt64 = (zc > 512) ? 1 : 0;
    }
}

__global__ void build_slots_kernel(const void* __restrict__ ei_raw, int E, int N) {
    int e = blockIdx.x * blockDim.x + threadIdx.x;
    if (e >= E) return;
    int s, d;
    if (g_fmt64) {
        const long long* ei = (const long long*)ei_raw;
        s = (int)ei[e];
        d = (int)ei[(size_t)E + e];
    } else {
        const int* ei = (const int*)ei_raw;
        s = ei[e];
        d = ei[E + e];
    }
    if ((unsigned)d >= (unsigned)N || (unsigned)s >= (unsigned)N) return;
    int p = atomicAdd(&g_deg[d], 1);
    if (p < SLOT_CAP) g_slots[d * SLOT_CAP + p] = s;
}

// ---------------- MMA helpers (baseline PTX, sm_103-safe) ----------------
__device__ __forceinline__ void mma_bf16(float& c0, float& c1, float& c2, float& c3,
                                         uint32_t a0, uint32_t a1, uint32_t a2, uint32_t a3,
                                         uint32_t b0, uint32_t b1) {
    asm volatile(
        "mma.sync.aligned.m16n8k16.row.col.f32.bf16.bf16.f32 "
        "{%0,%1,%2,%3}, {%4,%5,%6,%7}, {%8,%9}, {%0,%1,%2,%3};"
        : "+f"(c0), "+f"(c1), "+f"(c2), "+f"(c3)
        : "r"(a0), "r"(a1), "r"(a2), "r"(a3), "r"(b0), "r"(b1));
}
__device__ __forceinline__ void ldsm_x4(uint32_t& r0, uint32_t& r1, uint32_t& r2, uint32_t& r3,
                                        uint32_t addr) {
    asm volatile("ldmatrix.sync.aligned.m8n8.x4.shared.b16 {%0,%1,%2,%3}, [%4];"
                 : "=r"(r0), "=r"(r1), "=r"(r2), "=r"(r3) : "r"(addr));
}
__device__ __forceinline__ uint32_t smem_u32(const void* p) {
    uint32_t a;
    asm("{ .reg .u64 t; cvta.to.shared.u64 t, %1; cvt.u32.u64 %0, t; }" : "=r"(a) : "l"(p));
    return a;
}
__device__ __forceinline__ void cvt_pair(float2 v, uint32_t& hi, uint32_t& lo) {
    __nv_bfloat162 h = __floats2bfloat162_rn(v.x, v.y);
    float rx = v.x - __bfloat162float(h.x);
    float ry = v.y - __bfloat162float(h.y);
    __nv_bfloat162 l = __floats2bfloat162_rn(rx, ry);
    hi = *(uint32_t*)&h;
    lo = *(uint32_t*)&l;
}

// ---------------- GEMM: Gl = X@Wl^T (fp16 out), Gr = X@Wr^T (fp32 out) ----------------
#define NOUT 256
#define GEMM_SMEM (2 * NOUT * WROW + 16)

__global__ __launch_bounds__(GEMM_THREADS, 1) void gemm_kernel(
    const float* __restrict__ x,
    const float* __restrict__ Wl, const float* __restrict__ Wr, int N)
{
    extern __shared__ char smem[];
    char* Whi = smem;
    char* Wlo = smem + NOUT * WROW;
    int*  s_tile = (int*)(smem + 2 * NOUT * WROW);

    const int tid = threadIdx.x, wid = tid >> 5, lane = tid & 31;

    // Convert W' = [Wl;Wr] (256 out-rows x 128 k) to bf16 hi/lo in SMEM
    for (int idx = tid; idx < NOUT * (D / 2); idx += GEMM_THREADS) {
        int row = idx / (D / 2), kp = (idx % (D / 2)) * 2;
        const float* src = (row < 128) ? (Wl + row * D) : (Wr + (row - 128) * D);
        float2 v = *(const float2*)(src + kp);
        uint32_t hi, lo;
        cvt_pair(v, hi, lo);
        *(uint32_t*)(Whi + row * WROW + kp * 2) = hi;
        *(uint32_t*)(Wlo + row * WROW + kp * 2) = lo;
    }

    const int R      = (wid >> 1) * 16;
    const int nhalf  = (wid & 1) * 128;
    const int qr     = lane >> 2;
    const int qk     = (lane & 3) * 2;
    const int ln_row = lane & 7;
    const int ln_kg  = (lane >> 3) * 8;
    const uint32_t whi_base = smem_u32(Whi);
    const uint32_t wlo_base = smem_u32(Wlo);

    const int n_tiles = (N + TILE_M - 1) / TILE_M;

    for (;;) {
        if (tid == 0) *s_tile = atomicAdd(&g_tile_ctr, 1);
        __syncthreads();
        int tile = *s_tile;
        __syncthreads();
        if (tile >= n_tiles) break;
        int t = tile * TILE_M;

        // ---- A fragments from global (bf16 hi/lo), 8 k-blocks ----
        uint32_t ahi[8][4], alo[8][4];
        {
            int r0 = t + R + qr, r1 = r0 + 8;
            const float* p0 = x + (size_t)r0 * D + qk;
            const float* p1 = x + (size_t)r1 * D + qk;
            bool v0 = r0 < N, v1 = r1 < N;
            #pragma unroll
            for (int kb = 0; kb < 8; kb++) {
                float2 f0 = v0 ? *(const float2*)(p0 + kb * 16)     : make_float2(0.f, 0.f);
                float2 f1 = v1 ? *(const float2*)(p1 + kb * 16)     : make_float2(0.f, 0.f);
                float2 f2 = v0 ? *(const float2*)(p0 + kb * 16 + 8) : make_float2(0.f, 0.f);
                float2 f3 = v1 ? *(const float2*)(p1 + kb * 16 + 8) : make_float2(0.f, 0.f);
                cvt_pair(f0, ahi[kb][0], alo[kb][0]);
                cvt_pair(f1, ahi[kb][1], alo[kb][1]);
                cvt_pair(f2, ahi[kb][2], alo[kb][2]);
                cvt_pair(f3, ahi[kb][3], alo[kb][3]);
            }
        }

        // ---- 2 passes x 8 resident accumulators; nb INNER of kb-pair ->
        //      8 independent HMMA chains in flight (breaks acc serialization) ----
        #pragma unroll 1
        for (int pass = 0; pass < 2; pass++) {
            float acc[8][4];
            #pragma unroll
            for (int q = 0; q < 8; q++)
                { acc[q][0] = 0.f; acc[q][1] = 0.f; acc[q][2] = 0.f; acc[q][3] = 0.f; }

            #pragma unroll
            for (int c = 0; c < 4; c++) {               // kb-pair: kb = 2c, 2c+1
                #pragma unroll
                for (int q = 0; q < 8; q++) {           // nb within pass
                    int nb   = pass * 8 + q;
                    int nrow = nhalf + nb * 8 + ln_row;
                    uint32_t off = (uint32_t)nrow * WROW + (ln_kg + 32 * c) * 2;
                    uint32_t h0, h1, h2, h3, l0, l1, l2, l3;
                    ldsm_x4(h0, h1, h2, h3, whi_base + off);
                    ldsm_x4(l0, l1, l2, l3, wlo_base + off);
                    int kb0 = 2 * c, kb1 = 2 * c + 1;
                    mma_bf16(acc[q][0], acc[q][1], acc[q][2], acc[q][3],
                             ahi[kb0][0], ahi[kb0][1], ahi[kb0][2], ahi[kb0][3], h0, h1);
                    mma_bf16(acc[q][0], acc[q][1], acc[q][2], acc[q][3],
                             ahi[kb0][0], ahi[kb0][1], ahi[kb0][2], ahi[kb0][3], l0, l1);
                    mma_bf16(acc[q][0], acc[q][1], acc[q][2], acc[q][3],
                             alo[kb0][0], alo[kb0][1], alo[kb0][2], alo[kb0][3], h0, h1);
                    mma_bf16(acc[q][0], acc[q][1], acc[q][2], acc[q][3],
                             ahi[kb1][0], ahi[kb1][1], ahi[kb1][2], ahi[kb1][3], h2, h3);
                    mma_bf16(acc[q][0], acc[q][1], acc[q][2], acc[q][3],
                             ahi[kb1][0], ahi[kb1][1], ahi[kb1][2], ahi[kb1][3], l2, l3);
                    mma_bf16(acc[q][0], acc[q][1], acc[q][2], acc[q][3],
                             alo[kb1][0], alo[kb1][1], alo[kb1][2], alo[kb1][3], h2, h3);
                }
            }

            // ---- store this pass's 8 n-blocks ----
            int r0 = t + R + qr, r1 = r0 + 8;
            #pragma unroll
            for (int q = 0; q < 8; q++) {
                int col = (pass * 8 + q) * 8 + qk;      // col within 128-wide half
                if (nhalf == 0) {                        // Gl -> fp16
                    __half2 o0 = __floats2half2_rn(acc[q][0], acc[q][1]);
                    __half2 o1 = __floats2half2_rn(acc[q][2], acc[q][3]);
                    if (r0 < N) *(__half2*)(g_Gl + (size_t)r0 * D + col) = o0;
                    if (r1 < N) *(__half2*)(g_Gl + (size_t)r1 * D + col) = o1;
                } else {                                 // Gr -> fp32
                    if (r0 < N) *(float2*)(g_Gr + (size_t)r0 * D + col) = make_float2(acc[q][0], acc[q][1]);
                    if (r1 < N) *(float2*)(g_Gr + (size_t)r1 * D + col) = make_float2(acc[q][2], acc[q][3]);
                }
            }
        }
    }
}

// ---------------- aggregate: out_i = relu(LN(mean_j Gl[j] + Gr[i] + b)) ----------------
__global__ __launch_bounds__(256) void aggregate_kernel(
    const float* __restrict__ bl,
    const float* __restrict__ gamma, const float* __restrict__ beta,
    float* __restrict__ out, int N)
{
    int g    = (blockIdx.x * blockDim.x + threadIdx.x) >> 5;
    int lane = threadIdx.x & 31;
    if (g >= N) return;
    int c4 = lane * 4;

    float4 gr = *(const float4*)(g_Gr + (size_t)g * D + c4);
    int dg = g_deg[g];
    int m  = dg < SLOT_CAP ? dg : SLOT_CAP;
    const int* sl = g_slots + g * SLOT_CAP;

    float a0 = 0.f, a1 = 0.f, a2 = 0.f, a3 = 0.f;
    float b0 = 0.f, b1 = 0.f, b2 = 0.f, b3 = 0.f;
    int j = 0;
    for (; j + 3 < m; j += 4) {
        uint2 ua = *(const uint2*)(g_Gl + (size_t)sl[j]     * D + c4);
        uint2 ub = *(const uint2*)(g_Gl + (size_t)sl[j + 1] * D + c4);
        uint2 uc = *(const uint2*)(g_Gl + (size_t)sl[j + 2] * D + c4);
        uint2 ud = *(const uint2*)(g_Gl + (size_t)sl[j + 3] * D + c4);
        float2 fa0 = __half22float2(*(__half2*)&ua.x), fa1 = __half22float2(*(__half2*)&ua.y);
        float2 fb0 = __half22float2(*(__half2*)&ub.x), fb1 = __half22float2(*(__half2*)&ub.y);
        float2 fc0 = __half22float2(*(__half2*)&uc.x), fc1 = __half22float2(*(__half2*)&uc.y);
        float2 fd0 = __half22float2(*(__half2*)&ud.x), fd1 = __half22float2(*(__half2*)&ud.y);
        a0 += fa0.x + fb0.x; a1 += fa0.y + fb0.y; a2 += fa1.x + fb1.x; a3 += fa1.y + fb1.y;
        b0 += fc0.x + fd0.x; b1 += fc0.y + fd0.y; b2 += fc1.x + fd1.x; b3 += fc1.y + fd1.y;
    }
    for (; j < m; j++) {
        uint2 ua = *(const uint2*)(g_Gl + (size_t)sl[j] * D + c4);
        float2 fa0 = __half22float2(*(__half2*)&ua.x), fa1 = __half22float2(*(__half2*)&ua.y);
        a0 += fa0.x; a1 += fa0.y; a2 += fa1.x; a3 += fa1.y;
    }
    float ic = 1.0f / fmaxf((float)dg, 1.0f);
    float4 bb = *(const float4*)(bl + c4);
    float h0 = (a0 + b0) * ic + gr.x + bb.x;
    float h1 = (a1 + b1) * ic + gr.y + bb.y;
    float h2 = (a2 + b2) * ic + gr.z + bb.z;
    float h3 = (a3 + b3) * ic + gr.w + bb.w;

    float s1 = h0 + h1 + h2 + h3;
    float s2 = h0*h0 + h1*h1 + h2*h2 + h3*h3;
    #pragma unroll
    for (int off = 16; off > 0; off >>= 1) {
        s1 += __shfl_xor_sync(0xffffffffu, s1, off);
        s2 += __shfl_xor_sync(0xffffffffu, s2, off);
    }
    float mu  = s1 * (1.0f / D);
    float var = s2 * (1.0f / D) - mu * mu;
    float inv = rsqrtf(var + LN_EPS);

    float4 ga = *(const float4*)(gamma + c4);
    float4 be = *(const float4*)(beta + c4);
    float4 o;
    o.x = fmaxf((h0 - mu) * inv * ga.x + be.x, 0.f);
    o.y = fmaxf((h1 - mu) * inv * ga.y + be.y, 0.f);
    o.z = fmaxf((h2 - mu) * inv * ga.z + be.z, 0.f);
    o.w = fmaxf((h3 - mu) * inv * ga.w + be.w, 0.f);
    *(float4*)(out + g * D + c4) = o;
}

extern "C" void kernel_launch(void* const* d_in, const int* in_sizes, int n_in,
                              void* d_out, int out_size) {
    const float* x     = (const float*)d_in[0];
    const void*  ei    = d_in[1];
    const float* Wl    = (const float*)d_in[2];
    const float* bl    = (const float*)d_in[3];
    const float* Wr    = (const float*)d_in[4];
    const float* gamma = (const float*)d_in[5];
    const float* beta  = (const float*)d_in[6];
    float*       out   = (float*)d_out;

    int N = in_sizes[0] / D;
    int E = in_sizes[1] / 2;

    zero_probe_kernel<<<(N + 255) / 256, 256>>>((const int*)ei, N);
    build_slots_kernel<<<(E + 255) / 256, 256>>>(ei, E, N);

    cudaFuncSetAttribute(gemm_kernel,
                         cudaFuncAttributeMaxDynamicSharedMemorySize, GEMM_SMEM);
    gemm_kernel<<<NBLK, GEMM_THREADS, GEMM_SMEM>>>(x, Wl, Wr, N);

    int blocks = (N + 7) / 8;
    aggregate_kernel<<<blocks, 256>>>(bl, gamma, beta, out, N);
}